// round 11
// baseline (speedup 1.0000x reference)
#include <cuda_runtime.h>
#include <cstdint>

// ============================================================================
// QuantLinear: y = x @ (scales*q - zeros) + bias        (sm_100 portable path)
//   x:[32,4096] f32, qweight:[512,11008] i32 (8 nibbles/word along K),
//   scales/zeros/bias:[11008] f32, out:[32,11008] f32
//
// INT8 tensor-core path:
//   prep:  per token t: c_t = max|x|/32512; x ~= c_t*(256*h + l), h,l in s8
//          (exact s32 accumulation). Columns permuted (0,2,4,6,1,3,5,7)
//          within groups of 8 so B dequant is one shift+AND per fragment reg.
//          g_A rows 0-31 = h, rows 32-63 = l. S[t] = sum_k x_hat. Zeroes out.
//   gemm:  persistent-balanced: 86 N-tiles x 32 K-chunks = 2752 units over
//          296 CTAs (2/SM). 4-stage cp.async. mma.m16n8k32.s32.s8.s8 —
//          8 IMMA per k32 step (4 M-tiles x 2 n8 slices).
//          Epilogue: atomicAdd(out, s*c_t*(256*Dh+Dl) [+ b - S*z on chunk-0
//          segment]).
// ============================================================================

#define KTOT   4096
#define NTOT   11008
#define MTOK   32
#define TILE_N 128
#define TILE_K 128
#define NCHUNK 32
#define NTILES 86
#define UNITS  (NTILES * NCHUNK)  // 2752
#define GRID   296                // 2 x 148 SMs
#define THREADS 256
#define STAGES 4

#define STAGE_BYTES 16384         // A 8192 (64 rows x 128B) + Q 8192
#define SM_S (STAGES * STAGE_BYTES)
#define SMEM_TOTAL (SM_S + 256)   // + S[32] + c[32]

#define OUTN (MTOK * NTOT)

__device__ __align__(16) int8_t g_A[64 * KTOT];
__device__ float g_S[MTOK];
__device__ float g_c[MTOK];

// ---------------------------------------------------------------------------
__device__ __forceinline__ uint32_t smem_u32(const void* p) {
    uint32_t a;
    asm("{ .reg .u64 t; cvta.to.shared.u64 t, %1; cvt.u32.u64 %0, t; }"
        : "=r"(a) : "l"(p));
    return a;
}

#define CP16(dst, src) \
    asm volatile("cp.async.cg.shared.global [%0], [%1], 16;" :: "r"(dst), "l"(src))
#define CP_COMMIT() asm volatile("cp.async.commit_group;" ::: "memory")

__device__ __forceinline__ void imma16832(int* d, const uint32_t* a,
                                          uint32_t b0, uint32_t b1) {
    asm volatile(
        "mma.sync.aligned.m16n8k32.row.col.s32.s8.s8.s32 "
        "{%0,%1,%2,%3}, {%4,%5,%6,%7}, {%8,%9}, {%0,%1,%2,%3};"
        : "+r"(d[0]), "+r"(d[1]), "+r"(d[2]), "+r"(d[3])
        : "r"(a[0]), "r"(a[1]), "r"(a[2]), "r"(a[3]), "r"(b0), "r"(b1));
}

__device__ __forceinline__ void ldmx4(uint32_t* a, uint32_t addr) {
    asm volatile("ldmatrix.sync.aligned.m8n8.x4.shared.b16 {%0,%1,%2,%3}, [%4];"
                 : "=r"(a[0]), "=r"(a[1]), "=r"(a[2]), "=r"(a[3]) : "r"(addr));
}

__device__ __forceinline__ uint32_t lds32(uint32_t addr) {
    uint32_t v;
    asm volatile("ld.shared.b32 %0, [%1];" : "=r"(v) : "r"(addr));
    return v;
}

// ---------------------------------------------------------------------------
// prep: 32 blocks (one per token) x 256 threads; thread owns 16 k's.
// ---------------------------------------------------------------------------
__global__ void __launch_bounds__(256, 2) prep_kernel(const float* __restrict__ x,
                                                      float* __restrict__ out) {
    int t = blockIdx.x, tid = threadIdx.x;
    int wid = tid >> 5, lane = tid & 31;
    int k0 = tid * 16;

    float v[16];
    {
        const float4* p = (const float4*)(x + (size_t)t * KTOT + k0);
        float4 a = p[0], b = p[1], c4 = p[2], d = p[3];
        v[0]=a.x; v[1]=a.y; v[2]=a.z; v[3]=a.w;
        v[4]=b.x; v[5]=b.y; v[6]=b.z; v[7]=b.w;
        v[8]=c4.x; v[9]=c4.y; v[10]=c4.z; v[11]=c4.w;
        v[12]=d.x; v[13]=d.y; v[14]=d.z; v[15]=d.w;
    }
    float amax = 0.f;
    #pragma unroll
    for (int i = 0; i < 16; i++) amax = fmaxf(amax, fabsf(v[i]));
    #pragma unroll
    for (int off = 16; off; off >>= 1)
        amax = fmaxf(amax, __shfl_xor_sync(0xFFFFFFFFu, amax, off));
    __shared__ float redm[8];
    __shared__ float cSh;
    if (lane == 0) redm[wid] = amax;
    __syncthreads();
    if (tid == 0) {
        float m = redm[0];
        #pragma unroll
        for (int i = 1; i < 8; i++) m = fmaxf(m, redm[i]);
        cSh = fmaxf(m, 1e-30f) * (1.0f / 32512.0f);
    }
    __syncthreads();
    float c = cSh;
    float inv256c = 1.0f / (256.0f * c);
    float invc = 1.0f / c;

    int hq[16], lq[16];
    int hsum = 0, lsum = 0;
    #pragma unroll
    for (int i = 0; i < 16; i++) {
        float hf = rintf(v[i] * inv256c);
        int h = (int)hf;
        float r = fmaf(hf, -256.0f * c, v[i]);
        int l = (int)rintf(r * invc);
        if (l == 128) { l = -128; h += 1; }
        hsum += h; lsum += l;
        int g = i >> 3, j = i & 7;
        int p = (j >> 1) + ((j & 1) << 2);   // (0,2,4,6,1,3,5,7) permutation
        hq[g * 8 + p] = h;
        lq[g * 8 + p] = l;
    }
    uint32_t hw[4], lw[4];
    #pragma unroll
    for (int q = 0; q < 4; q++) {
        hw[q] = (hq[q*4] & 0xFF) | ((hq[q*4+1] & 0xFF) << 8) |
                ((hq[q*4+2] & 0xFF) << 16) | ((hq[q*4+3] & 0xFF) << 24);
        lw[q] = (lq[q*4] & 0xFF) | ((lq[q*4+1] & 0xFF) << 8) |
                ((lq[q*4+2] & 0xFF) << 16) | ((lq[q*4+3] & 0xFF) << 24);
    }
    *(uint4*)(g_A + (size_t)t * KTOT + k0) =
        make_uint4(hw[0], hw[1], hw[2], hw[3]);
    *(uint4*)(g_A + (size_t)(t + 32) * KTOT + k0) =
        make_uint4(lw[0], lw[1], lw[2], lw[3]);

    // reduce int sums
    #pragma unroll
    for (int off = 16; off; off >>= 1) {
        hsum += __shfl_xor_sync(0xFFFFFFFFu, hsum, off);
        lsum += __shfl_xor_sync(0xFFFFFFFFu, lsum, off);
    }
    __shared__ int redh[8], redl[8];
    if (lane == 0) { redh[wid] = hsum; redl[wid] = lsum; }
    __syncthreads();
    if (tid == 0) {
        int H = 0, L = 0;
        #pragma unroll
        for (int i = 0; i < 8; i++) { H += redh[i]; L += redl[i]; }
        g_S[t] = c * (256.0f * (float)H + (float)L);
        g_c[t] = c;
    }

    // zero out[] (float4 strided over all prep threads: 8192 threads)
    int gtid = t * 256 + tid;
    const float4 z4 = {0.f, 0.f, 0.f, 0.f};
    for (int i = gtid; i < OUTN / 4; i += 32 * 256)
        ((float4*)out)[i] = z4;
}

// ---------------------------------------------------------------------------
// gemm (persistent balanced, INT8)
// ---------------------------------------------------------------------------
__device__ __forceinline__ void issue_unit(uint32_t sb, int tid, int u, int slot,
                                           const int* __restrict__ qw) {
    int nt = u >> 5, cg = u & 31;
    int n0 = nt * TILE_N;
    uint32_t stage = sb + (uint32_t)slot * STAGE_BYTES;
    // A: 64 rows x 8 segs of 16B (swizzled), 512 segs
    #pragma unroll
    for (int i = 0; i < 2; i++) {
        int seg = tid + i * 256;
        int r = seg >> 3, cc = seg & 7;
        uint32_t dst = stage + r * 128 + (((uint32_t)cc ^ (uint32_t)(r & 7)) << 4);
        const char* src = (const char*)g_A + (size_t)r * KTOT + (size_t)cg * TILE_K + cc * 16;
        CP16(dst, src);
    }
    // Q: 16 kwords x 32 segs of 16B
    #pragma unroll
    for (int i = 0; i < 2; i++) {
        int seg = tid + i * 256;
        int kw = seg >> 5, ns = seg & 31;
        uint32_t dst = stage + 8192 + kw * 512 + ns * 16;
        const char* src = (const char*)qw + ((size_t)(cg * 16 + kw) * NTOT + n0) * 4 + ns * 16;
        CP16(dst, src);
    }
    CP_COMMIT();
}

__global__ void __launch_bounds__(THREADS, 2) gemm_kernel(
    const int* __restrict__ qw, const float* __restrict__ scales,
    const float* __restrict__ zeros, const float* __restrict__ bias,
    float* __restrict__ out) {
    extern __shared__ __align__(1024) char smem[];
    uint32_t sb = smem_u32(smem);
    int tid = threadIdx.x, wid = tid >> 5, lane = tid & 31;
    float* S_sm = (float*)(smem + SM_S);
    float* c_sm = (float*)(smem + SM_S + 128);

    int u0 = (int)(((long long)blockIdx.x * UNITS) / GRID);
    int u1 = (int)(((long long)(blockIdx.x + 1) * UNITS) / GRID);

    if (tid < 32) { S_sm[tid] = g_S[tid]; c_sm[tid] = g_c[tid]; }

    if (u0 + 0 < u1) issue_unit(sb, tid, u0 + 0, 0, qw);
    if (u0 + 1 < u1) issue_unit(sb, tid, u0 + 1, 1, qw);
    if (u0 + 2 < u1) issue_unit(sb, tid, u0 + 2, 2, qw);

    const int lrow = lane & 15;
    const int lcb  = lane >> 4;
    const int j4   = lane & 3;
    const int nrow = lane >> 2;
    const uint32_t sh = (uint32_t)((j4 & 1) * 4);
    const int tg2 = j4 >> 1;             // word select within k16 half

    int accH[2][2][4], accL[2][2][4];
    #pragma unroll
    for (int mt = 0; mt < 2; mt++)
        #pragma unroll
        for (int j = 0; j < 2; j++)
            #pragma unroll
            for (int i = 0; i < 4; i++) { accH[mt][j][i] = 0; accL[mt][j][i] = 0; }

    int seg_nt = u0 >> 5;
    bool seg_first = ((u0 & 31) == 0);

    for (int u = u0; u < u1; u++) {
        if (u + 2 < u1)      asm volatile("cp.async.wait_group 2;" ::: "memory");
        else if (u + 1 < u1) asm volatile("cp.async.wait_group 1;" ::: "memory");
        else                 asm volatile("cp.async.wait_group 0;" ::: "memory");
        __syncthreads();
        if (u + 3 < u1) issue_unit(sb, tid, u + 3, (u + 3 - u0) & (STAGES - 1), qw);

        uint32_t aBase = sb + (uint32_t)((u - u0) & (STAGES - 1)) * STAGE_BYTES;
        uint32_t qBase = aBase + 8192;
        // word addr for (kk, half, slice j): qBase + (kk*4 + tg2 + half*2)*512 + col*4
        uint32_t q0 = qBase + (uint32_t)tg2 * 512 + (uint32_t)(wid * 16 + nrow) * 4;
        uint32_t q1 = q0 + 8 * 4;        // slice 1 (cols +8)
        uint32_t aRow = aBase + (uint32_t)lrow * 128;
        uint32_t swz = (uint32_t)(lrow & 7) << 4;

        // w double-buffer: [buf][slice*2 + half]
        uint32_t w[2][4];
        w[0][0] = lds32(q0);
        w[0][1] = lds32(q0 + 1024);
        w[0][2] = lds32(q1);
        w[0][3] = lds32(q1 + 1024);

        #pragma unroll
        for (int kk = 0; kk < 4; kk++) {
            int cur = kk & 1, nx = cur ^ 1;
            // A: 4 m16 tiles (rows t*16), colblocks kk*2 + lcb
            uint32_t a[4][4];
            uint32_t ad = aRow + (((uint32_t)(kk * 2 + lcb) << 4) ^ swz);
            ldmx4(a[0], ad);
            ldmx4(a[1], ad + 16 * 128);
            ldmx4(a[2], ad + 32 * 128);
            ldmx4(a[3], ad + 48 * 128);
            if (kk < 3) {
                w[nx][0] = lds32(q0 + (kk + 1) * 2048);
                w[nx][1] = lds32(q0 + (kk + 1) * 2048 + 1024);
                w[nx][2] = lds32(q1 + (kk + 1) * 2048);
                w[nx][3] = lds32(q1 + (kk + 1) * 2048 + 1024);
            }
            uint32_t b00 = (w[cur][0] >> sh) & 0x0F0F0F0Fu;
            uint32_t b01 = (w[cur][1] >> sh) & 0x0F0F0F0Fu;
            uint32_t b10 = (w[cur][2] >> sh) & 0x0F0F0F0Fu;
            uint32_t b11 = (w[cur][3] >> sh) & 0x0F0F0F0Fu;

            imma16832(accH[0][0], a[0], b00, b01);
            imma16832(accH[1][0], a[1], b00, b01);
            imma16832(accL[0][0], a[2], b00, b01);
            imma16832(accL[1][0], a[3], b00, b01);
            imma16832(accH[0][1], a[0], b10, b11);
            imma16832(accH[1][1], a[1], b10, b11);
            imma16832(accL[0][1], a[2], b10, b11);
            imma16832(accL[1][1], a[3], b10, b11);
        }

        // flush at segment end (tile boundary or range end)
        bool last = (u + 1 == u1);
        if (last || ((u + 1) >> 5) != seg_nt) {
            int n0 = seg_nt * TILE_N;
            #pragma unroll
            for (int mt = 0; mt < 2; mt++) {
                #pragma unroll
                for (int j = 0; j < 2; j++) {
                    int ncl = wid * 16 + j * 8 + j4 * 2;
                    int col = n0 + ncl;
                    float s0 = __ldg(scales + col), s1 = __ldg(scales + col + 1);
                    int r0 = mt * 16 + nrow;
                    int r1 = r0 + 8;
                    float sc0 = s0 * c_sm[r0], sc1 = s1 * c_sm[r0];
                    float sd0 = s0 * c_sm[r1], sd1 = s1 * c_sm[r1];
                    float f00 = 256.0f * (float)accH[mt][j][0] + (float)accL[mt][j][0];
                    float f01 = 256.0f * (float)accH[mt][j][1] + (float)accL[mt][j][1];
                    float f10 = 256.0f * (float)accH[mt][j][2] + (float)accL[mt][j][2];
                    float f11 = 256.0f * (float)accH[mt][j][3] + (float)accL[mt][j][3];
                    float v00 = sc0 * f00, v01 = sc1 * f01;
                    float v10 = sd0 * f10, v11 = sd1 * f11;
                    if (seg_first) {
                        float z0 = __ldg(zeros + col), z1 = __ldg(zeros + col + 1);
                        float b0 = __ldg(bias + col),  b1 = __ldg(bias + col + 1);
                        float S0 = S_sm[r0], S1 = S_sm[r1];
                        v00 += b0 - S0 * z0;
                        v01 += b1 - S0 * z1;
                        v10 += b0 - S1 * z0;
                        v11 += b1 - S1 * z1;
                    }
                    atomicAdd(out + (size_t)r0 * NTOT + col,     v00);
                    atomicAdd(out + (size_t)r0 * NTOT + col + 1, v01);
                    atomicAdd(out + (size_t)r1 * NTOT + col,     v10);
                    atomicAdd(out + (size_t)r1 * NTOT + col + 1, v11);
                    #pragma unroll
                    for (int i = 0; i < 4; i++) { accH[mt][j][i] = 0; accL[mt][j][i] = 0; }
                }
            }
            if (!last) {
                seg_nt = (u + 1) >> 5;
                seg_first = true;
            }
        }
    }
}

// ---------------------------------------------------------------------------
extern "C" void kernel_launch(void* const* d_in, const int* in_sizes, int n_in,
                              void* d_out, int out_size) {
    const float* x      = (const float*)d_in[0];
    const int*   qw     = (const int*)d_in[1];
    const float* scales = (const float*)d_in[2];
    const float* zeros  = (const float*)d_in[3];
    const float* bias   = (const float*)d_in[4];
    float* out = (float*)d_out;

    cudaFuncSetAttribute(gemm_kernel, cudaFuncAttributeMaxDynamicSharedMemorySize, SMEM_TOTAL);

    prep_kernel<<<MTOK, 256>>>(x, out);
    gemm_kernel<<<GRID, THREADS, SMEM_TOTAL>>>(qw, scales, zeros, bias, out);
}